// round 1
// baseline (speedup 1.0000x reference)
#include <cuda_runtime.h>
#include <math.h>

// ---------------------------------------------------------------------------
// Problem constants: B=2, C=256, H=W=256, SSM=256, NH=16, HD=16, WS=8
// ---------------------------------------------------------------------------
#define PPLANE 65536            // H*W
#define NBATCH 2

// Scratch (device globals; no runtime allocation allowed)
__device__ float g_local[NBATCH * 256 * PPLANE];   // 134 MB
__device__ float g_qkv  [NBATCH * 768 * PPLANE];   // 402 MB
__device__ float g_attn [NBATCH * 256 * PPLANE];   // 134 MB
__device__ float g_mid  [NBATCH * 256 * PPLANE];   // 134 MB
__device__ float g_dw   [NBATCH * 256 * PPLANE];   // 134 MB

__device__ float g_inv1[256], g_inv2[256], g_biasc[256], g_invp[256], g_biasp[256];

// ---------------------------------------------------------------------------
// Prep: fold BN params
// ---------------------------------------------------------------------------
__global__ void prep_kernel(const float* __restrict__ g1, const float* __restrict__ b1,
                            const float* __restrict__ m1, const float* __restrict__ v1,
                            const float* __restrict__ g2, const float* __restrict__ b2,
                            const float* __restrict__ m2, const float* __restrict__ v2,
                            const float* __restrict__ gp, const float* __restrict__ bp,
                            const float* __restrict__ mp, const float* __restrict__ vp)
{
    int c = threadIdx.x;
    float i1 = g1[c] * rsqrtf(v1[c] + 1e-5f);
    float i2 = g2[c] * rsqrtf(v2[c] + 1e-5f);
    g_inv1[c] = i1;
    g_inv2[c] = i2;
    g_biasc[c] = (b1[c] - m1[c] * i1) + (b2[c] - m2[c] * i2);
    float ip = gp[c] * rsqrtf(vp[c] + 1e-5f);
    g_invp[c] = ip;
    g_biasp[c] = bp[c] - mp[c] * ip;
}

// ---------------------------------------------------------------------------
// Generic 128x128x16 SGEMM over "pixel" matrices.
//   C[(b*M + m)*65536 + p] = sum_k A[m*K+k] * B[(b*K + k)*65536 + p]
// dst: 0 -> g_qkv, 1 -> external extC.  Bm==nullptr -> use g_dw as B source.
// ---------------------------------------------------------------------------
__global__ __launch_bounds__(256) void gemm_plain(
    const float* __restrict__ A, const float* __restrict__ Bm,
    float* extC, int M, int K, int dst)
{
    __shared__ float As[16 * 128];
    __shared__ float Bs[16 * 128];
    const float* Bsrc = Bm ? Bm : (const float*)g_dw;
    float* C = (dst == 0) ? (float*)g_qkv : extC;

    int tid = threadIdx.x;
    int pg0 = blockIdx.x * 128;
    int b   = pg0 >> 16;
    int p0  = pg0 & 65535;
    int m0  = blockIdx.y * 128;

    int ty = tid >> 4, tx = tid & 15;

    // loaders
    int am = tid >> 1;
    int ak = (tid & 1) * 8;
    const float* Abase = A + (size_t)(m0 + am) * K + ak;
    int bk = tid >> 4;
    int bn = (tid & 15) * 8;
    const float* Bbase = Bsrc + ((size_t)(b * K + bk) << 16) + p0 + bn;

    float acc[8][8];
#pragma unroll
    for (int i = 0; i < 8; ++i)
#pragma unroll
        for (int j = 0; j < 8; ++j) acc[i][j] = 0.f;

    for (int k0 = 0; k0 < K; k0 += 16) {
        float4 a0 = *(const float4*)(Abase + k0);
        float4 a1 = *(const float4*)(Abase + k0 + 4);
        As[(ak + 0) * 128 + am] = a0.x;
        As[(ak + 1) * 128 + am] = a0.y;
        As[(ak + 2) * 128 + am] = a0.z;
        As[(ak + 3) * 128 + am] = a0.w;
        As[(ak + 4) * 128 + am] = a1.x;
        As[(ak + 5) * 128 + am] = a1.y;
        As[(ak + 6) * 128 + am] = a1.z;
        As[(ak + 7) * 128 + am] = a1.w;
        const float* bp = Bbase + ((size_t)k0 << 16);
        *(float4*)&Bs[bk * 128 + bn]     = *(const float4*)bp;
        *(float4*)&Bs[bk * 128 + bn + 4] = *(const float4*)(bp + 4);
        __syncthreads();
#pragma unroll
        for (int kk = 0; kk < 16; ++kk) {
            float4 A0 = *(const float4*)&As[kk * 128 + ty * 8];
            float4 A1 = *(const float4*)&As[kk * 128 + ty * 8 + 4];
            float4 B0 = *(const float4*)&Bs[kk * 128 + tx * 8];
            float4 B1 = *(const float4*)&Bs[kk * 128 + tx * 8 + 4];
            float av[8] = {A0.x, A0.y, A0.z, A0.w, A1.x, A1.y, A1.z, A1.w};
            float bv[8] = {B0.x, B0.y, B0.z, B0.w, B1.x, B1.y, B1.z, B1.w};
#pragma unroll
            for (int i = 0; i < 8; ++i)
#pragma unroll
                for (int j = 0; j < 8; ++j) acc[i][j] += av[i] * bv[j];
        }
        __syncthreads();
    }
#pragma unroll
    for (int i = 0; i < 8; ++i) {
        size_t row = ((size_t)(b * M + m0 + ty * 8 + i) << 16) + p0 + tx * 8;
        *(float4*)&C[row]     = make_float4(acc[i][0], acc[i][1], acc[i][2], acc[i][3]);
        *(float4*)&C[row + 4] = make_float4(acc[i][4], acc[i][5], acc[i][6], acc[i][7]);
    }
}

// ---------------------------------------------------------------------------
// Fused local branch: BN2(conv1x1(y,w2)) + BN1(conv3x3(y,w1)) as one implicit
// GEMM, K = 256*9 + 256 = 2560.  BN scale folded into A at load; combined bias
// in epilogue.  Writes g_local.
// ---------------------------------------------------------------------------
__global__ __launch_bounds__(256) void gemm_local(
    const float* __restrict__ w1, const float* __restrict__ w2,
    const float* __restrict__ y)
{
    __shared__ float As[16 * 128];
    __shared__ float Bs[16 * 128];

    int tid = threadIdx.x;
    int pg0 = blockIdx.x * 128;
    int b   = pg0 >> 16;
    int p0  = pg0 & 65535;
    int m0  = blockIdx.y * 128;
    int h   = p0 >> 8;
    int w0  = p0 & 255;

    int ty = tid >> 4, tx = tid & 15;

    int am = tid >> 1;
    int ak = (tid & 1) * 8;
    int mg = m0 + am;
    float s1 = g_inv1[mg];
    float s2 = g_inv2[mg];

    int bk = tid >> 4;
    int bn = (tid & 15) * 8;

    float acc[8][8];
#pragma unroll
    for (int i = 0; i < 8; ++i)
#pragma unroll
        for (int j = 0; j < 8; ++j) acc[i][j] = 0.f;

    for (int k0 = 0; k0 < 2560; k0 += 16) {
        // ---- A tile (8-run never straddles 2304 since 2304 % 16 == 0) ----
        {
            int k = k0 + ak;
            const float* ap;
            float sc;
            if (k < 2304) { ap = w1 + (size_t)mg * 2304 + k; sc = s1; }
            else          { ap = w2 + (size_t)mg * 256 + (k - 2304); sc = s2; }
            float4 a0 = *(const float4*)ap;
            float4 a1 = *(const float4*)(ap + 4);
            As[(ak + 0) * 128 + am] = a0.x * sc;
            As[(ak + 1) * 128 + am] = a0.y * sc;
            As[(ak + 2) * 128 + am] = a0.z * sc;
            As[(ak + 3) * 128 + am] = a0.w * sc;
            As[(ak + 4) * 128 + am] = a1.x * sc;
            As[(ak + 5) * 128 + am] = a1.y * sc;
            As[(ak + 6) * 128 + am] = a1.z * sc;
            As[(ak + 7) * 128 + am] = a1.w * sc;
        }
        // ---- B tile: shifted rows of y (zero-padded 3x3) or center (1x1) ----
        {
            int k = k0 + bk;
            int ci, dy, dx;
            if (k < 2304) {
                ci = k / 9;
                int tap = k - ci * 9;
                int r = tap / 3;
                dy = r - 1;
                dx = tap - r * 3 - 1;
            } else {
                ci = k - 2304; dy = 0; dx = 0;
            }
            int hh = h + dy;
            bool hok = (hh >= 0) && (hh < 256);
            const float* row = y + ((size_t)(b * 256 + ci) << 16) + hh * 256;
#pragma unroll
            for (int j = 0; j < 8; ++j) {
                int ww = w0 + bn + j + dx;
                float v = 0.f;
                if (hok && ww >= 0 && ww < 256) v = row[ww];
                Bs[bk * 128 + bn + j] = v;
            }
        }
        __syncthreads();
#pragma unroll
        for (int kk = 0; kk < 16; ++kk) {
            float4 A0 = *(const float4*)&As[kk * 128 + ty * 8];
            float4 A1 = *(const float4*)&As[kk * 128 + ty * 8 + 4];
            float4 B0 = *(const float4*)&Bs[kk * 128 + tx * 8];
            float4 B1 = *(const float4*)&Bs[kk * 128 + tx * 8 + 4];
            float av[8] = {A0.x, A0.y, A0.z, A0.w, A1.x, A1.y, A1.z, A1.w};
            float bv[8] = {B0.x, B0.y, B0.z, B0.w, B1.x, B1.y, B1.z, B1.w};
#pragma unroll
            for (int i = 0; i < 8; ++i)
#pragma unroll
                for (int j = 0; j < 8; ++j) acc[i][j] += av[i] * bv[j];
        }
        __syncthreads();
    }
#pragma unroll
    for (int i = 0; i < 8; ++i) {
        int m = m0 + ty * 8 + i;
        float bi = g_biasc[m];
        size_t row = ((size_t)(b * 256 + m) << 16) + p0 + tx * 8;
        *(float4*)&g_local[row] =
            make_float4(acc[i][0] + bi, acc[i][1] + bi, acc[i][2] + bi, acc[i][3] + bi);
        *(float4*)&g_local[row + 4] =
            make_float4(acc[i][4] + bi, acc[i][5] + bi, acc[i][6] + bi, acc[i][7] + bi);
    }
}

// ---------------------------------------------------------------------------
// Windowed attention: one block per (window, head); 64 threads = 64 tokens.
// q in regs (pre-scaled), k/v in smem, rpb column for this head in smem.
// ---------------------------------------------------------------------------
__global__ __launch_bounds__(64) void attn_kernel(const float* __restrict__ rpb,
                                                  float* __restrict__ unused)
{
    int win  = blockIdx.x;          // 0..2047
    int head = blockIdx.y;          // 0..15
    int b  = win >> 10;
    int wy = (win >> 5) & 31;
    int wx = win & 31;
    int i  = threadIdx.x;           // token
    int yi = i >> 3, xi = i & 7;
    int p  = ((wy * 8 + yi) << 8) + wx * 8 + xi;

    __shared__ float ks[64][16];
    __shared__ float vs[64][16];
    __shared__ float rpbs[225];

    for (int t = i; t < 225; t += 64) rpbs[t] = rpb[t * 16 + head];

    size_t base = ((size_t)(b * 768 + head * 16) << 16) + p;
    float q[16];
#pragma unroll
    for (int d = 0; d < 16; ++d) {
        q[d]     = g_qkv[base + ((size_t)d << 16)] * 0.25f;     // scale = HD^-0.5
        ks[i][d] = g_qkv[base + ((size_t)(256 + d) << 16)];
        vs[i][d] = g_qkv[base + ((size_t)(512 + d) << 16)];
    }
    __syncthreads();

    float s[64];
    float mx = -1e30f;
#pragma unroll
    for (int j = 0; j < 64; ++j) {
        const float4* kp = (const float4*)ks[j];
        float4 k0 = kp[0], k1 = kp[1], k2 = kp[2], k3 = kp[3];
        float acc = q[0] * k0.x + q[1] * k0.y + q[2] * k0.z + q[3] * k0.w
                  + q[4] * k1.x + q[5] * k1.y + q[6] * k1.z + q[7] * k1.w
                  + q[8] * k2.x + q[9] * k2.y + q[10] * k2.z + q[11] * k2.w
                  + q[12] * k3.x + q[13] * k3.y + q[14] * k3.z + q[15] * k3.w;
        int yj = j >> 3, xj = j & 7;
        acc += rpbs[(yi - yj + 7) * 15 + (xi - xj + 7)];
        s[j] = acc;
        mx = fmaxf(mx, acc);
    }
    float sum = 0.f;
#pragma unroll
    for (int j = 0; j < 64; ++j) { s[j] = __expf(s[j] - mx); sum += s[j]; }
    float inv = 1.f / sum;

    float o[16];
#pragma unroll
    for (int d = 0; d < 16; ++d) o[d] = 0.f;
#pragma unroll
    for (int j = 0; j < 64; ++j) {
        float pj = s[j] * inv;
        const float4* vp = (const float4*)vs[j];
        float4 v0 = vp[0], v1 = vp[1], v2 = vp[2], v3 = vp[3];
        o[0]  += pj * v0.x; o[1]  += pj * v0.y; o[2]  += pj * v0.z; o[3]  += pj * v0.w;
        o[4]  += pj * v1.x; o[5]  += pj * v1.y; o[6]  += pj * v1.z; o[7]  += pj * v1.w;
        o[8]  += pj * v2.x; o[9]  += pj * v2.y; o[10] += pj * v2.z; o[11] += pj * v2.w;
        o[12] += pj * v3.x; o[13] += pj * v3.y; o[14] += pj * v3.z; o[15] += pj * v3.w;
    }
#pragma unroll
    for (int d = 0; d < 16; ++d)
        g_attn[((size_t)(b * 256 + head * 16 + d) << 16) + p] = o[d];
}

// ---------------------------------------------------------------------------
// mid = avgpool_v(attn) + avgpool_h(attn) + local
// Both pools: 8-tap sums over t in [h-3, h+4]; index 256 reflects to 254,
// indices <0 or >256 contribute zero; divide by 8.
// ---------------------------------------------------------------------------
__global__ void pool_add_kernel()
{
    int bc = blockIdx.x >> 8;       // plane 0..511
    int h  = blockIdx.x & 255;
    int w  = threadIdx.x;
    const float* plane = g_attn + ((size_t)bc << 16);

    float sx = 0.f;
#pragma unroll
    for (int t = h - 3; t <= h + 4; ++t) {
        if (t >= 0 && t <= 256) {
            int tt = (t == 256) ? 254 : t;
            sx += plane[tt * 256 + w];
        }
    }
    const float* row = plane + h * 256;
    float sy = 0.f;
#pragma unroll
    for (int t = w - 3; t <= w + 4; ++t) {
        if (t >= 0 && t <= 256) {
            int tt = (t == 256) ? 254 : t;
            sy += row[tt];
        }
    }
    size_t idx = ((size_t)bc << 16) + h * 256 + w;
    g_mid[idx] = (sx + sy) * 0.125f + g_local[idx];
}

// ---------------------------------------------------------------------------
// Depthwise 8x8 conv on reflect(+1 bottom/right)-padded mid, zero pad 3, + BN.
// One block = one 32x32 output tile of one plane.  39x39 input tile in smem.
// ---------------------------------------------------------------------------
__global__ __launch_bounds__(256) void dwconv_kernel(const float* __restrict__ w_dw)
{
    __shared__ float tile[39 * 40];
    __shared__ float ws[64];

    int tix = blockIdx.x;           // 0..63
    int bc  = blockIdx.y;           // 0..511
    int c   = bc & 255;
    int ty0 = (tix >> 3) * 32;
    int tx0 = (tix & 7) * 32;
    int tid = threadIdx.x;

    const float* plane = g_mid + ((size_t)bc << 16);

    for (int idx = tid; idx < 39 * 39; idx += 256) {
        int r  = idx / 39;
        int cc = idx - r * 39;
        int gh = ty0 - 3 + r;
        int gw = tx0 - 3 + cc;
        float v = 0.f;
        if (gh >= 0 && gh <= 256 && gw >= 0 && gw <= 256) {
            int ih = (gh == 256) ? 254 : gh;
            int iw = (gw == 256) ? 254 : gw;
            v = plane[ih * 256 + iw];
        }
        tile[r * 40 + cc] = v;
    }
    if (tid < 64) ws[tid] = w_dw[c * 64 + tid];
    __syncthreads();

    int lw  = tid & 31;
    int lh0 = (tid >> 5) * 4;       // 4 vertically-adjacent outputs per thread
    float acc[4] = {0.f, 0.f, 0.f, 0.f};
#pragma unroll
    for (int j = 0; j < 8; ++j) {
        float wcol[8];
#pragma unroll
        for (int i = 0; i < 8; ++i) wcol[i] = ws[i * 8 + j];
#pragma unroll
        for (int r = 0; r < 11; ++r) {
            float v = tile[(lh0 + r) * 40 + lw + j];
#pragma unroll
            for (int a = 0; a < 4; ++a) {
                int i = r - a;
                if (i >= 0 && i < 8) acc[a] += v * wcol[i];
            }
        }
    }
    float ip = g_invp[c];
    float bb = g_biasp[c];
#pragma unroll
    for (int a = 0; a < 4; ++a) {
        int h = ty0 + lh0 + a;
        g_dw[((size_t)bc << 16) + h * 256 + tx0 + lw] = acc[a] * ip + bb;
    }
}

// ---------------------------------------------------------------------------
// Launch
// ---------------------------------------------------------------------------
extern "C" void kernel_launch(void* const* d_in, const int* in_sizes, int n_in,
                              void* d_out, int out_size)
{
    const float* x    = (const float*)d_in[0];
    const float* y    = (const float*)d_in[1];
    const float* wqkv = (const float*)d_in[2];
    const float* wl1  = (const float*)d_in[3];
    const float* g1   = (const float*)d_in[4];
    const float* b1   = (const float*)d_in[5];
    const float* m1   = (const float*)d_in[6];
    const float* v1   = (const float*)d_in[7];
    const float* wl2  = (const float*)d_in[8];
    const float* g2   = (const float*)d_in[9];
    const float* b2   = (const float*)d_in[10];
    const float* m2   = (const float*)d_in[11];
    const float* v2   = (const float*)d_in[12];
    const float* wdw  = (const float*)d_in[13];
    const float* gp   = (const float*)d_in[14];
    const float* bp   = (const float*)d_in[15];
    const float* mp   = (const float*)d_in[16];
    const float* vp   = (const float*)d_in[17];
    const float* wpw  = (const float*)d_in[18];
    const float* rpb  = (const float*)d_in[19];
    float* out = (float*)d_out;

    prep_kernel<<<1, 256>>>(g1, b1, m1, v1, g2, b2, m2, v2, gp, bp, mp, vp);

    // local branch: fused conv3x3 + conv1x1 + BNs
    gemm_local<<<dim3(1024, 2), 256>>>(wl1, wl2, y);

    // qkv = 1x1 conv (M=768, K=256) -> g_qkv
    gemm_plain<<<dim3(1024, 6), 256>>>(wqkv, x, nullptr, 768, 256, 0);

    // windowed attention -> g_attn
    attn_kernel<<<dim3(2048, 16), 64>>>(rpb, nullptr);

    // dual avg-pool + local -> g_mid
    pool_add_kernel<<<512 * 256, 256>>>();

    // depthwise 8x8 + BN -> g_dw
    dwconv_kernel<<<dim3(64, 512), 256>>>(wdw);

    // pointwise 1x1 (M=256, K=256), B = g_dw -> d_out
    gemm_plain<<<dim3(1024, 2), 256>>>(wpw, nullptr, out, 256, 256, 1);
}

// round 2
// speedup vs baseline: 1.0737x; 1.0737x over previous
#include <cuda_runtime.h>
#include <math.h>
#include <stdint.h>

// ---------------------------------------------------------------------------
// Problem constants: B=2, C=256, H=W=256, SSM=256, NH=16, HD=16, WS=8
// ---------------------------------------------------------------------------
#define PPLANE 65536
#define NBATCH 2

__device__ float g_local[NBATCH * 256 * PPLANE];
__device__ float g_qkv  [NBATCH * 768 * PPLANE];
__device__ float g_attn [NBATCH * 256 * PPLANE];
__device__ float g_mid  [NBATCH * 256 * PPLANE];
__device__ float g_dw   [NBATCH * 256 * PPLANE];

__device__ float g_inv1[256], g_inv2[256], g_biasc[256], g_invp[256], g_biasp[256];

// ---------------------------------------------------------------------------
// Helpers: split-TF32 and warp mma
// ---------------------------------------------------------------------------
__device__ __forceinline__ void split_tf32(float x, uint32_t& hi, uint32_t& lo)
{
    uint32_t h;
    asm("cvt.rna.tf32.f32 %0, %1;" : "=r"(h) : "f"(x));
    float r = x - __uint_as_float(h);
    asm("cvt.rna.tf32.f32 %0, %1;" : "=r"(lo) : "f"(r));
    hi = h;
}

__device__ __forceinline__ void mma8(float* c, const uint32_t* a, const uint32_t* b)
{
    asm volatile(
        "mma.sync.aligned.m16n8k8.row.col.f32.tf32.tf32.f32 "
        "{%0,%1,%2,%3},{%4,%5,%6,%7},{%8,%9},{%0,%1,%2,%3};"
        : "+f"(c[0]), "+f"(c[1]), "+f"(c[2]), "+f"(c[3])
        : "r"(a[0]), "r"(a[1]), "r"(a[2]), "r"(a[3]), "r"(b[0]), "r"(b[1]));
}

#define SA 136   // smem row stride (floats) -> conflict-free frag loads

__device__ __forceinline__ void ldAfrag(uint32_t af[4][4], const uint32_t* As,
                                        int ks, int wm, int lane)
{
    int g = lane >> 2, tig = lane & 3;
    const uint32_t* p0 = As + (ks + tig) * SA + wm + g;
    const uint32_t* p1 = As + (ks + tig + 4) * SA + wm + g;
#pragma unroll
    for (int mt = 0; mt < 4; ++mt) {
        af[mt][0] = p0[mt * 16];
        af[mt][1] = p0[mt * 16 + 8];
        af[mt][2] = p1[mt * 16];
        af[mt][3] = p1[mt * 16 + 8];
    }
}

__device__ __forceinline__ void ldBfrag(uint32_t bf[4][2], const uint32_t* Bs,
                                        int ks, int wn, int lane)
{
    int g = lane >> 2, tig = lane & 3;
    const uint32_t* p0 = Bs + (ks + tig) * SA + wn + g;
    const uint32_t* p1 = Bs + (ks + tig + 4) * SA + wn + g;
#pragma unroll
    for (int nt = 0; nt < 4; ++nt) {
        bf[nt][0] = p0[nt * 8];
        bf[nt][1] = p1[nt * 8];
    }
}

__device__ __forceinline__ void mma_all(float c[4][4][4], uint32_t af[4][4],
                                        uint32_t bf[4][2])
{
#pragma unroll
    for (int mt = 0; mt < 4; ++mt)
#pragma unroll
        for (int nt = 0; nt < 4; ++nt)
            mma8(c[mt][nt], af[mt], bf[nt]);
}

// ---------------------------------------------------------------------------
// Prep: fold BN params
// ---------------------------------------------------------------------------
__global__ void prep_kernel(const float* __restrict__ g1, const float* __restrict__ b1,
                            const float* __restrict__ m1, const float* __restrict__ v1,
                            const float* __restrict__ g2, const float* __restrict__ b2,
                            const float* __restrict__ m2, const float* __restrict__ v2,
                            const float* __restrict__ gp, const float* __restrict__ bp,
                            const float* __restrict__ mp, const float* __restrict__ vp)
{
    int c = threadIdx.x;
    float i1 = g1[c] * rsqrtf(v1[c] + 1e-5f);
    float i2 = g2[c] * rsqrtf(v2[c] + 1e-5f);
    g_inv1[c] = i1;
    g_inv2[c] = i2;
    g_biasc[c] = (b1[c] - m1[c] * i1) + (b2[c] - m2[c] * i2);
    float ip = gp[c] * rsqrtf(vp[c] + 1e-5f);
    g_invp[c] = ip;
    g_biasp[c] = bp[c] - mp[c] * ip;
}

// ---------------------------------------------------------------------------
// Split-TF32 tensor-core SGEMM, 128x128 tile, K-step 16.
//   C[(b*M+m)*65536 + p] = sum_k A[m*K+k] * B[(b*K+k)*65536 + p]
// ---------------------------------------------------------------------------
__global__ __launch_bounds__(256, 2) void gemm_tf32(
    const float* __restrict__ A, const float* __restrict__ Bm,
    float* extC, int M, int K, int dst)
{
    __shared__ uint32_t As_hi[16 * SA], As_lo[16 * SA];
    __shared__ uint32_t Bs_hi[16 * SA], Bs_lo[16 * SA];

    const float* Bsrc = Bm ? Bm : (const float*)g_dw;
    float* C = (dst == 0) ? (float*)g_qkv : extC;

    int tid = threadIdx.x;
    int pg0 = blockIdx.x * 128;
    int b   = pg0 >> 16;
    int p0  = pg0 & 65535;
    int m0  = blockIdx.y * 128;
    int lane = tid & 31, warp = tid >> 5;
    int wm = (warp >> 2) * 64, wn = (warp & 3) * 32;

    int am = tid >> 1, ak = (tid & 1) * 8;
    const float* Ab = A + (size_t)(m0 + am) * K + ak;
    int bk = tid >> 4, bn = (tid & 15) * 8;
    const float* Bb = Bsrc + ((size_t)(b * K + bk) << 16) + p0 + bn;

    float areg[8], breg[8];
    {
        float4 t0 = *(const float4*)Ab;
        float4 t1 = *(const float4*)(Ab + 4);
        areg[0]=t0.x; areg[1]=t0.y; areg[2]=t0.z; areg[3]=t0.w;
        areg[4]=t1.x; areg[5]=t1.y; areg[6]=t1.z; areg[7]=t1.w;
        float4 u0 = *(const float4*)Bb;
        float4 u1 = *(const float4*)(Bb + 4);
        breg[0]=u0.x; breg[1]=u0.y; breg[2]=u0.z; breg[3]=u0.w;
        breg[4]=u1.x; breg[5]=u1.y; breg[6]=u1.z; breg[7]=u1.w;
    }

    float c[4][4][4];
#pragma unroll
    for (int i = 0; i < 4; ++i)
#pragma unroll
        for (int j = 0; j < 4; ++j)
#pragma unroll
            for (int r = 0; r < 4; ++r) c[i][j][r] = 0.f;

    for (int k0 = 0; k0 < K; k0 += 16) {
#pragma unroll
        for (int j = 0; j < 8; ++j)
            split_tf32(areg[j], As_hi[(ak + j) * SA + am], As_lo[(ak + j) * SA + am]);
#pragma unroll
        for (int j = 0; j < 8; ++j)
            split_tf32(breg[j], Bs_hi[bk * SA + bn + j], Bs_lo[bk * SA + bn + j]);
        __syncthreads();

        if (k0 + 16 < K) {
            float4 t0 = *(const float4*)(Ab + k0 + 16);
            float4 t1 = *(const float4*)(Ab + k0 + 20);
            areg[0]=t0.x; areg[1]=t0.y; areg[2]=t0.z; areg[3]=t0.w;
            areg[4]=t1.x; areg[5]=t1.y; areg[6]=t1.z; areg[7]=t1.w;
            const float* bp = Bb + ((size_t)(k0 + 16) << 16);
            float4 u0 = *(const float4*)bp;
            float4 u1 = *(const float4*)(bp + 4);
            breg[0]=u0.x; breg[1]=u0.y; breg[2]=u0.z; breg[3]=u0.w;
            breg[4]=u1.x; breg[5]=u1.y; breg[6]=u1.z; breg[7]=u1.w;
        }

#pragma unroll
        for (int ks = 0; ks < 16; ks += 8) {
            uint32_t af[4][4], bf[4][2];
            ldAfrag(af, As_hi, ks, wm, lane);
            ldBfrag(bf, Bs_hi, ks, wn, lane);
            mma_all(c, af, bf);
            ldBfrag(bf, Bs_lo, ks, wn, lane);
            mma_all(c, af, bf);
            ldAfrag(af, As_lo, ks, wm, lane);
            ldBfrag(bf, Bs_hi, ks, wn, lane);
            mma_all(c, af, bf);
        }
        __syncthreads();
    }

    int g = lane >> 2, tig = lane & 3;
#pragma unroll
    for (int mt = 0; mt < 4; ++mt) {
        int r0 = m0 + wm + mt * 16 + g;
#pragma unroll
        for (int nt = 0; nt < 4; ++nt) {
            int col = p0 + wn + nt * 8 + tig * 2;
            size_t i0 = ((size_t)(b * M + r0) << 16) + col;
            size_t i1 = ((size_t)(b * M + r0 + 8) << 16) + col;
            *(float2*)&C[i0] = make_float2(c[mt][nt][0], c[mt][nt][1]);
            *(float2*)&C[i1] = make_float2(c[mt][nt][2], c[mt][nt][3]);
        }
    }
}

// ---------------------------------------------------------------------------
// Fused local branch (conv3x3+BN1 + conv1x1+BN2) as split-TF32 implicit GEMM,
// K = 2304 + 256 = 2560.  BN scale folded at A load; combined bias epilogue.
// ---------------------------------------------------------------------------
__global__ __launch_bounds__(256, 2) void gemm_local_tf32(
    const float* __restrict__ w1, const float* __restrict__ w2,
    const float* __restrict__ y)
{
    __shared__ uint32_t As_hi[16 * SA], As_lo[16 * SA];
    __shared__ uint32_t Bs_hi[16 * SA], Bs_lo[16 * SA];

    int tid = threadIdx.x;
    int pg0 = blockIdx.x * 128;
    int b   = pg0 >> 16;
    int p0  = pg0 & 65535;
    int m0  = blockIdx.y * 128;
    int hrow = p0 >> 8;
    int w0   = p0 & 255;
    int lane = tid & 31, warp = tid >> 5;
    int wm = (warp >> 2) * 64, wn = (warp & 3) * 32;

    int am = tid >> 1, ak = (tid & 1) * 8;
    int mg = m0 + am;
    float s1 = g_inv1[mg];
    float s2 = g_inv2[mg];
    int bk = tid >> 4, bn = (tid & 15) * 8;

    float areg[8], breg[8];

    auto loadA = [&](int k0) {
        int k = k0 + ak;
        const float* ap;
        float sc;
        if (k < 2304) { ap = w1 + (size_t)mg * 2304 + k; sc = s1; }
        else          { ap = w2 + (size_t)mg * 256 + (k - 2304); sc = s2; }
        float4 t0 = *(const float4*)ap;
        float4 t1 = *(const float4*)(ap + 4);
        areg[0]=t0.x*sc; areg[1]=t0.y*sc; areg[2]=t0.z*sc; areg[3]=t0.w*sc;
        areg[4]=t1.x*sc; areg[5]=t1.y*sc; areg[6]=t1.z*sc; areg[7]=t1.w*sc;
    };
    auto loadB = [&](int k0) {
        int k = k0 + bk;
        int ci, dy, dx;
        if (k < 2304) {
            ci = k / 9;
            int tap = k - ci * 9;
            int r = tap / 3;
            dy = r - 1;
            dx = tap - r * 3 - 1;
        } else {
            ci = k - 2304; dy = 0; dx = 0;
        }
        int hh = hrow + dy;
        bool hok = (hh >= 0) && (hh < 256);
        const float* row = y + ((size_t)(b * 256 + ci) << 16) + hh * 256;
#pragma unroll
        for (int j = 0; j < 8; ++j) {
            int ww = w0 + bn + j + dx;
            breg[j] = (hok && ww >= 0 && ww < 256) ? row[ww] : 0.f;
        }
    };

    loadA(0);
    loadB(0);

    float c[4][4][4];
#pragma unroll
    for (int i = 0; i < 4; ++i)
#pragma unroll
        for (int j = 0; j < 4; ++j)
#pragma unroll
            for (int r = 0; r < 4; ++r) c[i][j][r] = 0.f;

    for (int k0 = 0; k0 < 2560; k0 += 16) {
#pragma unroll
        for (int j = 0; j < 8; ++j)
            split_tf32(areg[j], As_hi[(ak + j) * SA + am], As_lo[(ak + j) * SA + am]);
#pragma unroll
        for (int j = 0; j < 8; ++j)
            split_tf32(breg[j], Bs_hi[bk * SA + bn + j], Bs_lo[bk * SA + bn + j]);
        __syncthreads();

        if (k0 + 16 < 2560) { loadA(k0 + 16); loadB(k0 + 16); }

#pragma unroll
        for (int ks = 0; ks < 16; ks += 8) {
            uint32_t af[4][4], bf[4][2];
            ldAfrag(af, As_hi, ks, wm, lane);
            ldBfrag(bf, Bs_hi, ks, wn, lane);
            mma_all(c, af, bf);
            ldBfrag(bf, Bs_lo, ks, wn, lane);
            mma_all(c, af, bf);
            ldAfrag(af, As_lo, ks, wm, lane);
            ldBfrag(bf, Bs_hi, ks, wn, lane);
            mma_all(c, af, bf);
        }
        __syncthreads();
    }

    int g = lane >> 2, tig = lane & 3;
#pragma unroll
    for (int mt = 0; mt < 4; ++mt) {
        int r0 = m0 + wm + mt * 16 + g;
        float bi0 = g_biasc[r0];
        float bi1 = g_biasc[r0 + 8];
#pragma unroll
        for (int nt = 0; nt < 4; ++nt) {
            int col = p0 + wn + nt * 8 + tig * 2;
            size_t i0 = ((size_t)(b * 256 + r0) << 16) + col;
            size_t i1 = ((size_t)(b * 256 + r0 + 8) << 16) + col;
            *(float2*)&g_local[i0] = make_float2(c[mt][nt][0] + bi0, c[mt][nt][1] + bi0);
            *(float2*)&g_local[i1] = make_float2(c[mt][nt][2] + bi1, c[mt][nt][3] + bi1);
        }
    }
}

// ---------------------------------------------------------------------------
// Windowed attention, online softmax (no s[64] spill).
// One block per (window, head); 64 threads = 64 tokens.
// ---------------------------------------------------------------------------
__global__ __launch_bounds__(64) void attn_kernel(const float* __restrict__ rpb)
{
    int win  = blockIdx.x;
    int head = blockIdx.y;
    int b  = win >> 10;
    int wy = (win >> 5) & 31;
    int wx = win & 31;
    int i  = threadIdx.x;
    int yi = i >> 3, xi = i & 7;
    int p  = ((wy * 8 + yi) << 8) + wx * 8 + xi;

    __shared__ float ks[64][16];
    __shared__ float vs[64][16];
    __shared__ float rpbs[225];

    for (int t = i; t < 225; t += 64) rpbs[t] = rpb[t * 16 + head];

    size_t base = ((size_t)(b * 768 + head * 16) << 16) + p;
    float q[16];
#pragma unroll
    for (int d = 0; d < 16; ++d) {
        q[d]     = g_qkv[base + ((size_t)d << 16)] * 0.25f;
        ks[i][d] = g_qkv[base + ((size_t)(256 + d) << 16)];
        vs[i][d] = g_qkv[base + ((size_t)(512 + d) << 16)];
    }
    __syncthreads();

    float m_run = -1e30f, l_run = 0.f;
    float o[16];
#pragma unroll
    for (int d = 0; d < 16; ++d) o[d] = 0.f;

#pragma unroll
    for (int cchunk = 0; cchunk < 4; ++cchunk) {
        float s[16];
        float cm = -1e30f;
#pragma unroll
        for (int jj = 0; jj < 16; ++jj) {
            int j = cchunk * 16 + jj;
            const float4* kp = (const float4*)ks[j];
            float4 k0 = kp[0], k1 = kp[1], k2 = kp[2], k3 = kp[3];
            float acc = q[0] * k0.x + q[1] * k0.y + q[2] * k0.z + q[3] * k0.w
                      + q[4] * k1.x + q[5] * k1.y + q[6] * k1.z + q[7] * k1.w
                      + q[8] * k2.x + q[9] * k2.y + q[10] * k2.z + q[11] * k2.w
                      + q[12] * k3.x + q[13] * k3.y + q[14] * k3.z + q[15] * k3.w;
            int yj = j >> 3, xj = j & 7;
            acc += rpbs[(yi - yj + 7) * 15 + (xi - xj + 7)];
            s[jj] = acc;
            cm = fmaxf(cm, acc);
        }
        float mnew = fmaxf(m_run, cm);
        float corr = __expf(m_run - mnew);
        l_run *= corr;
#pragma unroll
        for (int d = 0; d < 16; ++d) o[d] *= corr;
#pragma unroll
        for (int jj = 0; jj < 16; ++jj) {
            int j = cchunk * 16 + jj;
            float pj = __expf(s[jj] - mnew);
            l_run += pj;
            const float4* vp = (const float4*)vs[j];
            float4 v0 = vp[0], v1 = vp[1], v2 = vp[2], v3 = vp[3];
            o[0]  += pj * v0.x; o[1]  += pj * v0.y; o[2]  += pj * v0.z; o[3]  += pj * v0.w;
            o[4]  += pj * v1.x; o[5]  += pj * v1.y; o[6]  += pj * v1.z; o[7]  += pj * v1.w;
            o[8]  += pj * v2.x; o[9]  += pj * v2.y; o[10] += pj * v2.z; o[11] += pj * v2.w;
            o[12] += pj * v3.x; o[13] += pj * v3.y; o[14] += pj * v3.z; o[15] += pj * v3.w;
        }
        m_run = mnew;
    }
    float inv = 1.f / l_run;
#pragma unroll
    for (int d = 0; d < 16; ++d)
        g_attn[((size_t)(b * 256 + head * 16 + d) << 16) + p] = o[d] * inv;
}

// ---------------------------------------------------------------------------
// mid = avgpool_v(attn) + avgpool_h(attn) + local
// ---------------------------------------------------------------------------
__global__ void pool_add_kernel()
{
    int bc = blockIdx.x >> 8;
    int h  = blockIdx.x & 255;
    int w  = threadIdx.x;
    const float* plane = g_attn + ((size_t)bc << 16);

    float sx = 0.f;
#pragma unroll
    for (int t = h - 3; t <= h + 4; ++t) {
        if (t >= 0 && t <= 256) {
            int tt = (t == 256) ? 254 : t;
            sx += plane[tt * 256 + w];
        }
    }
    const float* row = plane + h * 256;
    float sy = 0.f;
#pragma unroll
    for (int t = w - 3; t <= w + 4; ++t) {
        if (t >= 0 && t <= 256) {
            int tt = (t == 256) ? 254 : t;
            sy += row[tt];
        }
    }
    size_t idx = ((size_t)bc << 16) + h * 256 + w;
    g_mid[idx] = (sx + sy) * 0.125f + g_local[idx];
}

// ---------------------------------------------------------------------------
// Depthwise 8x8 conv + BN
// ---------------------------------------------------------------------------
__global__ __launch_bounds__(256) void dwconv_kernel(const float* __restrict__ w_dw)
{
    __shared__ float tile[39 * 40];
    __shared__ float ws[64];

    int tix = blockIdx.x;
    int bc  = blockIdx.y;
    int c   = bc & 255;
    int ty0 = (tix >> 3) * 32;
    int tx0 = (tix & 7) * 32;
    int tid = threadIdx.x;

    const float* plane = g_mid + ((size_t)bc << 16);

    for (int idx = tid; idx < 39 * 39; idx += 256) {
        int r  = idx / 39;
        int cc = idx - r * 39;
        int gh = ty0 - 3 + r;
        int gw = tx0 - 3 + cc;
        float v = 0.f;
        if (gh >= 0 && gh <= 256 && gw >= 0 && gw <= 256) {
            int ih = (gh == 256) ? 254 : gh;
            int iw = (gw == 256) ? 254 : gw;
            v = plane[ih * 256 + iw];
        }
        tile[r * 40 + cc] = v;
    }
    if (tid < 64) ws[tid] = w_dw[c * 64 + tid];
    __syncthreads();

    int lw  = tid & 31;
    int lh0 = (tid >> 5) * 4;
    float acc[4] = {0.f, 0.f, 0.f, 0.f};
#pragma unroll
    for (int j = 0; j < 8; ++j) {
        float wcol[8];
#pragma unroll
        for (int i = 0; i < 8; ++i) wcol[i] = ws[i * 8 + j];
#pragma unroll
        for (int r = 0; r < 11; ++r) {
            float v = tile[(lh0 + r) * 40 + lw + j];
#pragma unroll
            for (int a = 0; a < 4; ++a) {
                int i = r - a;
                if (i >= 0 && i < 8) acc[a] += v * wcol[i];
            }
        }
    }
    float ip = g_invp[c];
    float bb = g_biasp[c];
#pragma unroll
    for (int a = 0; a < 4; ++a) {
        int h = ty0 + lh0 + a;
        g_dw[((size_t)bc << 16) + h * 256 + tx0 + lw] = acc[a] * ip + bb;
    }
}

// ---------------------------------------------------------------------------
// Launch
// ---------------------------------------------------------------------------
extern "C" void kernel_launch(void* const* d_in, const int* in_sizes, int n_in,
                              void* d_out, int out_size)
{
    const float* x    = (const float*)d_in[0];
    const float* y    = (const float*)d_in[1];
    const float* wqkv = (const float*)d_in[2];
    const float* wl1  = (const float*)d_in[3];
    const float* g1   = (const float*)d_in[4];
    const float* b1   = (const float*)d_in[5];
    const float* m1   = (const float*)d_in[6];
    const float* v1   = (const float*)d_in[7];
    const float* wl2  = (const float*)d_in[8];
    const float* g2   = (const float*)d_in[9];
    const float* b2   = (const float*)d_in[10];
    const float* m2   = (const float*)d_in[11];
    const float* v2   = (const float*)d_in[12];
    const float* wdw  = (const float*)d_in[13];
    const float* gp   = (const float*)d_in[14];
    const float* bp   = (const float*)d_in[15];
    const float* mp   = (const float*)d_in[16];
    const float* vp   = (const float*)d_in[17];
    const float* wpw  = (const float*)d_in[18];
    const float* rpb  = (const float*)d_in[19];
    float* out = (float*)d_out;

    prep_kernel<<<1, 256>>>(g1, b1, m1, v1, g2, b2, m2, v2, gp, bp, mp, vp);

    gemm_local_tf32<<<dim3(1024, 2), 256>>>(wl1, wl2, y);

    gemm_tf32<<<dim3(1024, 6), 256>>>(wqkv, x, nullptr, 768, 256, 0);

    attn_kernel<<<dim3(2048, 16), 64>>>(rpb);

    pool_add_kernel<<<512 * 256, 256>>>();

    dwconv_kernel<<<dim3(64, 512), 256>>>(wdw);

    gemm_tf32<<<dim3(1024, 2), 256>>>(wpw, nullptr, out, 256, 256, 1);
}